// round 11
// baseline (speedup 1.0000x reference)
#include <cuda_runtime.h>
#include <cuda_fp16.h>
#include <mma.h>
#include <cstdint>

using namespace nvcuda;

#define BS   4
#define TN   512
#define DM   512
#define HN   8
#define HDN  64
#define LN_  6
#define VN   50257
#define VNP  50304          // VN padded to multiple of 128
#define EPSV 1e-5f

// ---------------- scratch ----------------
__device__ float  g_h   [BS*TN*DM];          // residual stream (fp32)
__device__ __half g_tmpH[BS*TN*DM];          // LN output (fp16, GEMM A)
__device__ __half g_qkvA[BS*TN*3*DM];        // qkv activations (fp16)
__device__ __half g_attH[BS*TN*DM];          // attention output (fp16, GEMM A)
__device__ __half g_ffH [BS*TN*4*DM];        // ff1 output (fp16, GEMM A)
// fp16 weights ([K,N] row-major)
__device__ __half g_qkvH[LN_*DM*3*DM];
__device__ __half g_outH[LN_*DM*DM];
__device__ __half g_ff1H[LN_*DM*4*DM];
__device__ __half g_ff2H[LN_*4*DM*DM];
__device__ __half g_headH[DM*VNP];           // zero-padded

// ---------------- weight conversion (vectorized: 4 elems/thread) ----------------
__global__ void convh_k(const float* __restrict__ src, __half* __restrict__ dst, int n4) {
    int i = blockIdx.x * 256 + threadIdx.x;
    if (i >= n4) return;
    float4 v = *(const float4*)&src[i * 4];
    __half2* d = (__half2*)&dst[i * 4];
    d[0] = __floats2half2_rn(v.x, v.y);
    d[1] = __floats2half2_rn(v.z, v.w);
}
__global__ void convpad_k(const float* __restrict__ src, __half* __restrict__ dst) {
    int n = (blockIdx.x * 256 + threadIdx.x) * 4;
    int k = blockIdx.y;
    if (n >= VNP) return;
    const float* sp = src + (size_t)k * VN;
    float a = (n + 0 < VN) ? sp[n + 0] : 0.0f;
    float b = (n + 1 < VN) ? sp[n + 1] : 0.0f;
    float c = (n + 2 < VN) ? sp[n + 2] : 0.0f;
    float d = (n + 3 < VN) ? sp[n + 3] : 0.0f;
    __half2* dp = (__half2*)&dst[(size_t)k * VNP + n];
    dp[0] = __floats2half2_rn(a, b);
    dp[1] = __floats2half2_rn(c, d);
}

// ---------------- embedding ----------------
__global__ void embed_k(const int* __restrict__ x, const float* __restrict__ tok,
                        const float* __restrict__ pos, float* __restrict__ h) {
    int i = blockIdx.x * 256 + threadIdx.x;
    if (i >= BS*TN*DM) return;
    int d  = i % DM;
    int bt = i / DM;
    int t  = bt % TN;
    h[i] = tok[(size_t)x[bt] * DM + d] + pos[t * DM + d];
}

// ---------------- layernorm: warp per row, 8 rows/CTA ----------------
__global__ __launch_bounds__(256) void ln_k(const float* __restrict__ in, __half* __restrict__ out,
                                            const float* __restrict__ sc, const float* __restrict__ bi) {
    int warp = threadIdx.x >> 5, lane = threadIdx.x & 31;
    int row = blockIdx.x * 8 + warp;
    const float4* xr = (const float4*)(in + (size_t)row * DM);
    float4 v[4];
    float s1 = 0.0f, s2 = 0.0f;
    #pragma unroll
    for (int i = 0; i < 4; i++) {
        v[i] = xr[lane + i * 32];
        s1 += v[i].x + v[i].y + v[i].z + v[i].w;
        s2 += v[i].x*v[i].x + v[i].y*v[i].y + v[i].z*v[i].z + v[i].w*v[i].w;
    }
    #pragma unroll
    for (int o = 16; o; o >>= 1) {
        s1 += __shfl_xor_sync(0xffffffffu, s1, o);
        s2 += __shfl_xor_sync(0xffffffffu, s2, o);
    }
    float mean = s1 * (1.0f / DM);
    float r = rsqrtf(s2 * (1.0f / DM) - mean * mean + EPSV);
    const float4* sc4 = (const float4*)sc;
    const float4* bi4 = (const float4*)bi;
    __half2* op = (__half2*)(out + (size_t)row * DM);
    #pragma unroll
    for (int i = 0; i < 4; i++) {
        int ch = lane + i * 32;
        float4 g = sc4[ch], bb = bi4[ch];
        float4 x = v[i];
        op[ch * 2]     = __floats2half2_rn((x.x - mean) * r * g.x + bb.x,
                                           (x.y - mean) * r * g.y + bb.y);
        op[ch * 2 + 1] = __floats2half2_rn((x.z - mean) * r * g.z + bb.z,
                                           (x.w - mean) * r * g.w + bb.w);
    }
}

// ---------------- epilogue store helpers ----------------
__device__ __forceinline__ void stval(float* C, size_t i, float v)  { C[i] = v; }
__device__ __forceinline__ void stval(__half* C, size_t i, float v) { C[i] = __float2half(v); }

// ---------------- fp16 wmma GEMM, 2-stage cp.async, dynamic smem ----------------
// C[M,N] = A[M,K](fp16) @ B[K,N](fp16) + bias (+epilogue), fp32 accumulate.
// MODE 0: bias; 1: bias + exact gelu; 2: bias + residual.
// Bs = B row stride (>= N, multiple of 8). 16B-aligned cp.async by construction.
template <int BM, int BN, int BK, int NT, int WR, int WC, int MODE, typename OT>
__global__ __launch_bounds__(NT) void gemmh(const __half* __restrict__ A,
                                            const __half* __restrict__ B,
                                            const float* __restrict__ bias,
                                            const float* __restrict__ res,
                                            OT* __restrict__ C,
                                            int M, int N, int K, int Bs) {
    constexpr int LDA = BK + 8;
    constexpr int LDB = BN + 8;
    constexpr int WTM = BM / WR;
    constexpr int WTN = BN / WC;
    constexpr int FM  = WTM / 16;
    constexpr int FN  = WTN / 16;
    constexpr int CHA = BK / 8;               // 16B chunks per A row
    constexpr int CHB = BN / 8;               // 16B chunks per B row
    constexpr int IA  = (BM * CHA) / NT;
    constexpr int IB  = (BK * CHB) / NT;
    constexpr int SZA = BM * LDA;             // halves per A stage
    constexpr int SZB = BK * LDB;             // halves per B stage

    extern __shared__ char dsm[];
    __half* smA = (__half*)dsm;
    __half* smB = smA + 2 * SZA;

    const int tid  = threadIdx.x;
    const int warp = tid >> 5;
    const int lane = tid & 31;
    const int wm   = warp / WC;
    const int wn   = warp % WC;
    const int m0   = blockIdx.x * BM;
    const int n0   = blockIdx.y * BN;

    const uint32_t sA0 = (uint32_t)__cvta_generic_to_shared(smA);
    const uint32_t sB0 = (uint32_t)__cvta_generic_to_shared(smB);

    wmma::fragment<wmma::accumulator, 16, 16, 16, float> acc[FM][FN];
    #pragma unroll
    for (int i = 0; i < FM; i++)
        #pragma unroll
        for (int j = 0; j < FN; j++)
            wmma::fill_fragment(acc[i][j], 0.0f);

    auto issue = [&](int buf, int k0) {
        #pragma unroll
        for (int i = 0; i < IA; i++) {
            int idx = tid + i * NT;
            int r = idx / CHA, c = (idx % CHA) * 8;
            uint32_t dst = sA0 + (uint32_t)(buf * SZA + r * LDA + c) * 2u;
            const __half* src = A + (size_t)(m0 + r) * K + k0 + c;
            asm volatile("cp.async.cg.shared.global [%0], [%1], 16;" :: "r"(dst), "l"(src));
        }
        #pragma unroll
        for (int i = 0; i < IB; i++) {
            int idx = tid + i * NT;
            int r = idx / CHB, c = (idx % CHB) * 8;
            uint32_t dst = sB0 + (uint32_t)(buf * SZB + r * LDB + c) * 2u;
            const __half* src = B + (size_t)(k0 + r) * Bs + n0 + c;
            asm volatile("cp.async.cg.shared.global [%0], [%1], 16;" :: "r"(dst), "l"(src));
        }
    };

    const int nst = K / BK;

    issue(0, 0);
    asm volatile("cp.async.commit_group;" ::: "memory");

    for (int s = 0; s < nst; s++) {
        if (s + 1 < nst) {
            issue((s + 1) & 1, (s + 1) * BK);
            asm volatile("cp.async.commit_group;" ::: "memory");
            asm volatile("cp.async.wait_group 1;" ::: "memory");
        } else {
            asm volatile("cp.async.wait_group 0;" ::: "memory");
        }
        __syncthreads();

        const int buf = s & 1;
        const __half* pa = smA + buf * SZA;
        const __half* pb = smB + buf * SZB;
        #pragma unroll
        for (int ks = 0; ks < BK; ks += 16) {
            wmma::fragment<wmma::matrix_a, 16, 16, 16, __half, wmma::row_major> af[FM];
            wmma::fragment<wmma::matrix_b, 16, 16, 16, __half, wmma::row_major> bf[FN];
            #pragma unroll
            for (int i = 0; i < FM; i++)
                wmma::load_matrix_sync(af[i], pa + (wm * WTM + i * 16) * LDA + ks, LDA);
            #pragma unroll
            for (int j = 0; j < FN; j++)
                wmma::load_matrix_sync(bf[j], pb + ks * LDB + wn * WTN + j * 16, LDB);
            #pragma unroll
            for (int i = 0; i < FM; i++)
                #pragma unroll
                for (int j = 0; j < FN; j++)
                    wmma::mma_sync(acc[i][j], af[i], bf[j], acc[i][j]);
        }
        __syncthreads();
    }

    // fused epilogue via per-warp smem patch (pipeline smem is dead)
    float* patch = (float*)dsm + warp * (16 * 20);
    #pragma unroll
    for (int i = 0; i < FM; i++)
        #pragma unroll
        for (int j = 0; j < FN; j++) {
            wmma::store_matrix_sync(patch, acc[i][j], 20, wmma::mem_row_major);
            __syncwarp();
            const int rg0 = m0 + wm * WTM + i * 16;
            const int cg0 = n0 + wn * WTN + j * 16;
            #pragma unroll
            for (int e = 0; e < 8; e++) {
                int li  = lane * 8 + e;
                int r   = li >> 4;
                int c   = li & 15;
                int col = cg0 + c;
                if (col < N) {
                    size_t gi = (size_t)(rg0 + r) * N + col;
                    float v = patch[r * 20 + c] + bias[col];
                    if (MODE == 1) v = 0.5f * v * (1.0f + erff(v * 0.70710678118654752f));
                    if (MODE == 2) v += res[gi];
                    stval(C, gi, v);
                }
            }
            __syncwarp();
        }
}

// smem bytes for a config
#define GSMEM(BM_, BN_, BK_) (2 * ((BM_) * ((BK_) + 8) + (BK_) * ((BN_) + 8)) * 2)

// ---------------- fused flash attention ----------------
// One CTA = (b, h, 64-row q tile). 4 warps. qkv fp16 in, O fp16 out.
#define ATT_SMEM (4 * 64 * 72 * 2 + 2 * 64 * 68 * 4 + 2 * 64 * 4)

__global__ __launch_bounds__(128) void fattn_k(const __half* __restrict__ qkv,
                                               __half* __restrict__ o) {
    int bh = blockIdx.y;
    int b  = bh >> 3;
    int h  = bh & 7;
    int q0 = blockIdx.x << 6;
    int tid = threadIdx.x, warp = tid >> 5, lane = tid & 31;

    extern __shared__ char smem[];
    __half* Qs = (__half*)smem;             // 64*72
    __half* Ks = Qs + 64 * 72;
    __half* Vs = Ks + 64 * 72;
    __half* Ph = Vs + 64 * 72;
    float*  Sf = (float*)(Ph + 64 * 72);    // 64*68
    float*  Of = Sf + 64 * 68;
    float*  mrow = Of + 64 * 68;
    float*  lrow = mrow + 64;

    const uint32_t sQ = (uint32_t)__cvta_generic_to_shared(Qs);
    const uint32_t sK = (uint32_t)__cvta_generic_to_shared(Ks);
    const uint32_t sV = (uint32_t)__cvta_generic_to_shared(Vs);

    #pragma unroll
    for (int i = 0; i < 4; i++) {
        int idx = tid + i * 128;
        int r = idx >> 3, c = (idx & 7) * 8;
        uint32_t dst = sQ + (uint32_t)(r * 72 + c) * 2u;
        const __half* src = qkv + ((size_t)(b * TN + q0 + r)) * 1536 + h * 64 + c;
        asm volatile("cp.async.cg.shared.global [%0], [%1], 16;" :: "r"(dst), "l"(src));
    }
    asm volatile("cp.async.commit_group;" ::: "memory");

    for (int i = tid; i < 64 * 68; i += 128) Of[i] = 0.0f;
    if (tid < 64) { mrow[tid] = -1e30f; lrow[tid] = 0.0f; }

    const int jmax = q0 >> 6;
    for (int j = 0; j <= jmax; j++) {
        const int j0 = j << 6;
        #pragma unroll
        for (int i = 0; i < 4; i++) {
            int idx = tid + i * 128;
            int r = idx >> 3, c = (idx & 7) * 8;
            const __half* srcK = qkv + ((size_t)(b * TN + j0 + r)) * 1536 + 512 + h * 64 + c;
            const __half* srcV = qkv + ((size_t)(b * TN + j0 + r)) * 1536 + 1024 + h * 64 + c;
            uint32_t dK = sK + (uint32_t)(r * 72 + c) * 2u;
            uint32_t dV = sV + (uint32_t)(r * 72 + c) * 2u;
            asm volatile("cp.async.cg.shared.global [%0], [%1], 16;" :: "r"(dK), "l"(srcK));
            asm volatile("cp.async.cg.shared.global [%0], [%1], 16;" :: "r"(dV), "l"(srcV));
        }
        asm volatile("cp.async.commit_group;" ::: "memory");
        asm volatile("cp.async.wait_group 0;" ::: "memory");
        __syncthreads();

        // S = Q @ K^T (fp32 acc), warp w -> rows [w*16, w*16+16)
        {
            wmma::fragment<wmma::matrix_a, 16, 16, 16, __half, wmma::row_major> af;
            wmma::fragment<wmma::matrix_b, 16, 16, 16, __half, wmma::col_major> bf;
            wmma::fragment<wmma::accumulator, 16, 16, 16, float> ac[4];
            #pragma unroll
            for (int n = 0; n < 4; n++) wmma::fill_fragment(ac[n], 0.0f);
            #pragma unroll
            for (int k = 0; k < 4; k++) {
                wmma::load_matrix_sync(af, Qs + (warp * 16) * 72 + k * 16, 72);
                #pragma unroll
                for (int n = 0; n < 4; n++) {
                    wmma::load_matrix_sync(bf, Ks + (n * 16) * 72 + k * 16, 72);
                    wmma::mma_sync(ac[n], af, bf, ac[n]);
                }
            }
            #pragma unroll
            for (int n = 0; n < 4; n++)
                wmma::store_matrix_sync(Sf + (warp * 16) * 68 + n * 16, ac[n], 68,
                                        wmma::mem_row_major);
        }
        __syncthreads();

        // online softmax: 2 threads per row
        {
            int r  = tid >> 1;
            int hc = (tid & 1) * 32;
            bool diag = (j == jmax);
            float* srow = Sf + r * 68 + hc;
            float sv[32];
            float lm = -1e30f;
            #pragma unroll
            for (int c = 0; c < 32; c++) {
                float s = srow[c] * 0.125f;
                if (diag && (hc + c) > r) s = -1e30f;
                sv[c] = s;
                lm = fmaxf(lm, s);
            }
            float mt = fmaxf(lm, __shfl_xor_sync(0xffffffffu, lm, 1));
            float mo = mrow[r];
            float mn = fmaxf(mo, mt);
            float fs = expf(mo - mn);
            float sum = 0.0f;
            __half* prow = Ph + r * 72 + hc;
            #pragma unroll
            for (int c = 0; c < 32; c++) {
                float p = expf(sv[c] - mn);
                prow[c] = __float2half(p);
                sum += p;
            }
            sum += __shfl_xor_sync(0xffffffffu, sum, 1);
            float* orow = Of + r * 68 + hc;
            #pragma unroll
            for (int c = 0; c < 32; c++) orow[c] *= fs;
            __syncwarp();
            if ((tid & 1) == 0) {
                mrow[r] = mn;
                lrow[r] = lrow[r] * fs + sum;
            }
        }
        __syncthreads();

        // O += P @ V
        {
            wmma::fragment<wmma::matrix_a, 16, 16, 16, __half, wmma::row_major> af;
            wmma::fragment<wmma::matrix_b, 16, 16, 16, __half, wmma::row_major> bf;
            wmma::fragment<wmma::accumulator, 16, 16, 16, float> ac;
            #pragma unroll
            for (int n = 0; n < 4; n++) {
                wmma::load_matrix_sync(ac, Of + (warp * 16) * 68 + n * 16, 68,
                                       wmma::mem_row_major);
                #pragma unroll
                for (int k = 0; k < 4; k++) {
                    wmma::load_matrix_sync(af, Ph + (warp * 16) * 72 + k * 16, 72);
                    wmma::load_matrix_sync(bf, Vs + (k * 16) * 72 + n * 16, 72);
                    wmma::mma_sync(ac, af, bf, ac);
                }
                wmma::store_matrix_sync(Of + (warp * 16) * 68 + n * 16, ac, 68,
                                        wmma::mem_row_major);
            }
        }
        __syncthreads();
    }

    // epilogue: O / l -> fp16
    {
        int r  = tid >> 1;
        int hc = (tid & 1) * 32;
        float inv = 1.0f / lrow[r];
        float* orow = Of + r * 68 + hc;
        __half* dst = o + ((size_t)(b * TN + q0 + r)) * DM + h * 64 + hc;
        #pragma unroll
        for (int c = 0; c < 32; c++)
            dst[c] = __float2half(orow[c] * inv);
    }
}

// ---------------- launch ----------------
extern "C" void kernel_launch(void* const* d_in, const int* in_sizes, int n_in,
                              void* d_out, int out_size) {
    const int*   x      = (const int*)  d_in[0];
    const float* tok    = (const float*)d_in[1];
    const float* pos    = (const float*)d_in[2];
    const float* qkv_w  = (const float*)d_in[3];
    const float* qkv_b  = (const float*)d_in[4];
    const float* out_w  = (const float*)d_in[5];
    const float* out_b  = (const float*)d_in[6];
    const float* ln1_s  = (const float*)d_in[7];
    const float* ln1_b  = (const float*)d_in[8];
    const float* ff1_w  = (const float*)d_in[9];
    const float* ff1_b  = (const float*)d_in[10];
    const float* ff2_w  = (const float*)d_in[11];
    const float* ff2_b  = (const float*)d_in[12];
    const float* ln2_s  = (const float*)d_in[13];
    const float* ln2_b  = (const float*)d_in[14];
    const float* lnf_s  = (const float*)d_in[15];
    const float* lnf_b  = (const float*)d_in[16];
    const float* head_w = (const float*)d_in[17];
    const float* head_b = (const float*)d_in[18];
    float* out = (float*)d_out;

    float *h;
    __half *tmpH, *qkvA, *attH, *ffH, *qkvH, *outH, *ff1H, *ff2H, *headH;
    cudaGetSymbolAddress((void**)&h,    g_h);
    cudaGetSymbolAddress((void**)&tmpH, g_tmpH);
    cudaGetSymbolAddress((void**)&qkvA, g_qkvA);
    cudaGetSymbolAddress((void**)&attH, g_attH);
    cudaGetSymbolAddress((void**)&ffH,  g_ffH);
    cudaGetSymbolAddress((void**)&qkvH, g_qkvH);
    cudaGetSymbolAddress((void**)&outH, g_outH);
    cudaGetSymbolAddress((void**)&ff1H, g_ff1H);
    cudaGetSymbolAddress((void**)&ff2H, g_ff2H);
    cudaGetSymbolAddress((void**)&headH,g_headH);

    const int M = BS * TN;  // 2048
    const int SMBIG = GSMEM(128, 128, 64);   // 71680 B
    const int SMSML = GSMEM(64, 64, 32);     // 19456 B

    cudaFuncSetAttribute(gemmh<128,128,64,128,2,2,0,__half>, cudaFuncAttributeMaxDynamicSharedMemorySize, SMBIG);
    cudaFuncSetAttribute(gemmh<128,128,64,128,2,2,1,__half>, cudaFuncAttributeMaxDynamicSharedMemorySize, SMBIG);
    cudaFuncSetAttribute(gemmh<128,128,64,128,2,2,0,float>,  cudaFuncAttributeMaxDynamicSharedMemorySize, SMBIG);
    cudaFuncSetAttribute(fattn_k, cudaFuncAttributeMaxDynamicSharedMemorySize, ATT_SMEM);

    // weight conversions (fp32 -> fp16), 4 elems/thread
    {
        int n4;
        n4 = LN_*DM*3*DM/4;  convh_k<<<(n4+255)/256, 256>>>(qkv_w, qkvH, n4);
        n4 = LN_*DM*DM/4;    convh_k<<<(n4+255)/256, 256>>>(out_w, outH, n4);
        n4 = LN_*DM*4*DM/4;  convh_k<<<(n4+255)/256, 256>>>(ff1_w, ff1H, n4);
        n4 = LN_*4*DM*DM/4;  convh_k<<<(n4+255)/256, 256>>>(ff2_w, ff2H, n4);
        convpad_k<<<dim3((VNP/4+255)/256, DM), 256>>>(head_w, headH);
    }

    embed_k<<<(BS*TN*DM + 255) / 256, 256>>>(x, tok, pos, h);

    for (int l = 0; l < LN_; l++) {
        const __half* wq = qkvH + (size_t)l * DM * 3*DM;
        const __half* wo = outH + (size_t)l * DM * DM;
        const __half* w1 = ff1H + (size_t)l * DM * 4*DM;
        const __half* w2 = ff2H + (size_t)l * 4*DM * DM;
        const float* bq = qkv_b + (size_t)l * 3*DM;
        const float* bo = out_b + (size_t)l * DM;
        const float* b1 = ff1_b + (size_t)l * 4*DM;
        const float* b2 = ff2_b + (size_t)l * DM;

        // attention block
        ln_k<<<M / 8, 256>>>(h, tmpH, ln1_s + l * DM, ln1_b + l * DM);
        gemmh<128,128,64,128,2,2,0,__half><<<dim3(16, 12), 128, SMBIG>>>(tmpH, wq, bq, nullptr, qkvA, M, 3*DM, DM, 3*DM);
        fattn_k<<<dim3(8, 32), 128, ATT_SMEM>>>(qkvA, attH);
        gemmh<64,64,32,32,1,1,2,float><<<dim3(32, 8), 32, SMSML>>>(attH, wo, bo, h, h, M, DM, DM, DM);

        // feed-forward block
        ln_k<<<M / 8, 256>>>(h, tmpH, ln2_s + l * DM, ln2_b + l * DM);
        gemmh<128,128,64,128,2,2,1,__half><<<dim3(16, 16), 128, SMBIG>>>(tmpH, w1, b1, nullptr, ffH, M, 4*DM, DM, 4*DM);
        gemmh<64,64,32,32,1,1,2,float><<<dim3(32, 8), 32, SMSML>>>(ffH, w2, b2, h, h, M, DM, 4*DM, DM);
    }

    // final LN + LM head
    ln_k<<<M / 8, 256>>>(h, tmpH, lnf_s, lnf_b);
    gemmh<128,128,64,128,2,2,0,float><<<dim3(16, VNP / 128), 128, SMBIG>>>(tmpH, headH, head_b, nullptr, out, M, VN, DM, VNP);
}

// round 13
// speedup vs baseline: 1.0772x; 1.0772x over previous
#include <cuda_runtime.h>
#include <cuda_fp16.h>
#include <mma.h>
#include <cstdint>

using namespace nvcuda;

#define BS   4
#define TN   512
#define DM   512
#define HN   8
#define HDN  64
#define LN_  6
#define VN   50257
#define VNP  50304          // VN padded to multiple of 128
#define EPSV 1e-5f

// ---------------- scratch ----------------
__device__ float  g_h   [BS*TN*DM];          // residual stream (fp32)
__device__ __half g_tmpH[BS*TN*DM];          // LN output (fp16, GEMM A)
__device__ __half g_qkvA[BS*TN*3*DM];        // qkv activations (fp16)
__device__ __half g_attH[BS*TN*DM];          // attention output (fp16, GEMM A)
__device__ __half g_ffH [BS*TN*4*DM];        // ff1 output (fp16, GEMM A)
// fp16 weights ([K,N] row-major)
__device__ __half g_qkvH[LN_*DM*3*DM];
__device__ __half g_outH[LN_*DM*DM];
__device__ __half g_ff1H[LN_*DM*4*DM];
__device__ __half g_ff2H[LN_*4*DM*DM];
__device__ __half g_headH[DM*VNP];           // zero-padded

// ---------------- weight conversion (vectorized: 4 elems/thread) ----------------
__global__ void convh_k(const float* __restrict__ src, __half* __restrict__ dst, int n4) {
    int i = blockIdx.x * 256 + threadIdx.x;
    if (i >= n4) return;
    float4 v = *(const float4*)&src[i * 4];
    __half2* d = (__half2*)&dst[i * 4];
    d[0] = __floats2half2_rn(v.x, v.y);
    d[1] = __floats2half2_rn(v.z, v.w);
}
__global__ void convpad_k(const float* __restrict__ src, __half* __restrict__ dst) {
    int n = (blockIdx.x * 256 + threadIdx.x) * 4;
    int k = blockIdx.y;
    if (n >= VNP) return;
    const float* sp = src + (size_t)k * VN;
    float a = (n + 0 < VN) ? sp[n + 0] : 0.0f;
    float b = (n + 1 < VN) ? sp[n + 1] : 0.0f;
    float c = (n + 2 < VN) ? sp[n + 2] : 0.0f;
    float d = (n + 3 < VN) ? sp[n + 3] : 0.0f;
    __half2* dp = (__half2*)&dst[(size_t)k * VNP + n];
    dp[0] = __floats2half2_rn(a, b);
    dp[1] = __floats2half2_rn(c, d);
}

// ---------------- embedding ----------------
__global__ void embed_k(const int* __restrict__ x, const float* __restrict__ tok,
                        const float* __restrict__ pos, float* __restrict__ h) {
    int i = blockIdx.x * 256 + threadIdx.x;
    if (i >= BS*TN*DM) return;
    int d  = i % DM;
    int bt = i / DM;
    int t  = bt % TN;
    h[i] = tok[(size_t)x[bt] * DM + d] + pos[t * DM + d];
}

// ---------------- layernorm: warp per row, 8 rows/CTA ----------------
__global__ __launch_bounds__(256) void ln_k(const float* __restrict__ in, __half* __restrict__ out,
                                            const float* __restrict__ sc, const float* __restrict__ bi) {
    int warp = threadIdx.x >> 5, lane = threadIdx.x & 31;
    int row = blockIdx.x * 8 + warp;
    const float4* xr = (const float4*)(in + (size_t)row * DM);
    float4 v[4];
    float s1 = 0.0f, s2 = 0.0f;
    #pragma unroll
    for (int i = 0; i < 4; i++) {
        v[i] = xr[lane + i * 32];
        s1 += v[i].x + v[i].y + v[i].z + v[i].w;
        s2 += v[i].x*v[i].x + v[i].y*v[i].y + v[i].z*v[i].z + v[i].w*v[i].w;
    }
    #pragma unroll
    for (int o = 16; o; o >>= 1) {
        s1 += __shfl_xor_sync(0xffffffffu, s1, o);
        s2 += __shfl_xor_sync(0xffffffffu, s2, o);
    }
    float mean = s1 * (1.0f / DM);
    float r = rsqrtf(s2 * (1.0f / DM) - mean * mean + EPSV);
    const float4* sc4 = (const float4*)sc;
    const float4* bi4 = (const float4*)bi;
    __half2* op = (__half2*)(out + (size_t)row * DM);
    #pragma unroll
    for (int i = 0; i < 4; i++) {
        int ch = lane + i * 32;
        float4 g = sc4[ch], bb = bi4[ch];
        float4 x = v[i];
        op[ch * 2]     = __floats2half2_rn((x.x - mean) * r * g.x + bb.x,
                                           (x.y - mean) * r * g.y + bb.y);
        op[ch * 2 + 1] = __floats2half2_rn((x.z - mean) * r * g.z + bb.z,
                                           (x.w - mean) * r * g.w + bb.w);
    }
}

// ---------------- epilogue store helpers ----------------
__device__ __forceinline__ void stval(float* C, size_t i, float v)  { C[i] = v; }
__device__ __forceinline__ void stval(__half* C, size_t i, float v) { C[i] = __float2half(v); }

// ---------------- fp16 wmma GEMM, 2-stage cp.async, dynamic smem ----------------
// C[M,N] = A[M,K](fp16) @ B[K,N](fp16) + bias (+epilogue), fp32 accumulate.
// MODE 0: bias; 1: bias + exact gelu; 2: bias + residual.
// Bs = B row stride (>= N, multiple of 8). 16B-aligned cp.async by construction.
template <int BM, int BN, int BK, int NT, int WR, int WC, int MODE, typename OT>
__global__ __launch_bounds__(NT) void gemmh(const __half* __restrict__ A,
                                            const __half* __restrict__ B,
                                            const float* __restrict__ bias,
                                            const float* __restrict__ res,
                                            OT* __restrict__ C,
                                            int M, int N, int K, int Bs) {
    constexpr int LDA = BK + 8;
    constexpr int LDB = BN + 8;
    constexpr int WTM = BM / WR;
    constexpr int WTN = BN / WC;
    constexpr int FM  = WTM / 16;
    constexpr int FN  = WTN / 16;
    constexpr int CHA = BK / 8;               // 16B chunks per A row
    constexpr int CHB = BN / 8;               // 16B chunks per B row
    constexpr int IA  = (BM * CHA) / NT;
    constexpr int IB  = (BK * CHB) / NT;
    constexpr int SZA = BM * LDA;             // halves per A stage
    constexpr int SZB = BK * LDB;             // halves per B stage

    extern __shared__ char dsm[];
    __half* smA = (__half*)dsm;
    __half* smB = smA + 2 * SZA;

    const int tid  = threadIdx.x;
    const int warp = tid >> 5;
    const int lane = tid & 31;
    const int wm   = warp / WC;
    const int wn   = warp % WC;
    const int m0   = blockIdx.x * BM;
    const int n0   = blockIdx.y * BN;

    const uint32_t sA0 = (uint32_t)__cvta_generic_to_shared(smA);
    const uint32_t sB0 = (uint32_t)__cvta_generic_to_shared(smB);

    wmma::fragment<wmma::accumulator, 16, 16, 16, float> acc[FM][FN];
    #pragma unroll
    for (int i = 0; i < FM; i++)
        #pragma unroll
        for (int j = 0; j < FN; j++)
            wmma::fill_fragment(acc[i][j], 0.0f);

    auto issue = [&](int buf, int k0) {
        #pragma unroll
        for (int i = 0; i < IA; i++) {
            int idx = tid + i * NT;
            int r = idx / CHA, c = (idx % CHA) * 8;
            uint32_t dst = sA0 + (uint32_t)(buf * SZA + r * LDA + c) * 2u;
            const __half* src = A + (size_t)(m0 + r) * K + k0 + c;
            asm volatile("cp.async.cg.shared.global [%0], [%1], 16;" :: "r"(dst), "l"(src));
        }
        #pragma unroll
        for (int i = 0; i < IB; i++) {
            int idx = tid + i * NT;
            int r = idx / CHB, c = (idx % CHB) * 8;
            uint32_t dst = sB0 + (uint32_t)(buf * SZB + r * LDB + c) * 2u;
            const __half* src = B + (size_t)(k0 + r) * Bs + n0 + c;
            asm volatile("cp.async.cg.shared.global [%0], [%1], 16;" :: "r"(dst), "l"(src));
        }
    };

    const int nst = K / BK;

    issue(0, 0);
    asm volatile("cp.async.commit_group;" ::: "memory");

    for (int s = 0; s < nst; s++) {
        if (s + 1 < nst) {
            issue((s + 1) & 1, (s + 1) * BK);
            asm volatile("cp.async.commit_group;" ::: "memory");
            asm volatile("cp.async.wait_group 1;" ::: "memory");
        } else {
            asm volatile("cp.async.wait_group 0;" ::: "memory");
        }
        __syncthreads();

        const int buf = s & 1;
        const __half* pa = smA + buf * SZA;
        const __half* pb = smB + buf * SZB;
        #pragma unroll
        for (int ks = 0; ks < BK; ks += 16) {
            wmma::fragment<wmma::matrix_a, 16, 16, 16, __half, wmma::row_major> af[FM];
            wmma::fragment<wmma::matrix_b, 16, 16, 16, __half, wmma::row_major> bf[FN];
            #pragma unroll
            for (int i = 0; i < FM; i++)
                wmma::load_matrix_sync(af[i], pa + (wm * WTM + i * 16) * LDA + ks, LDA);
            #pragma unroll
            for (int j = 0; j < FN; j++)
                wmma::load_matrix_sync(bf[j], pb + ks * LDB + wn * WTN + j * 16, LDB);
            #pragma unroll
            for (int i = 0; i < FM; i++)
                #pragma unroll
                for (int j = 0; j < FN; j++)
                    wmma::mma_sync(acc[i][j], af[i], bf[j], acc[i][j]);
        }
        __syncthreads();
    }

    // fused epilogue via per-warp smem patch (pipeline smem is dead)
    float* patch = (float*)dsm + warp * (16 * 20);
    #pragma unroll
    for (int i = 0; i < FM; i++)
        #pragma unroll
        for (int j = 0; j < FN; j++) {
            wmma::store_matrix_sync(patch, acc[i][j], 20, wmma::mem_row_major);
            __syncwarp();
            const int rg0 = m0 + wm * WTM + i * 16;
            const int cg0 = n0 + wn * WTN + j * 16;
            #pragma unroll
            for (int e = 0; e < 8; e++) {
                int li  = lane * 8 + e;
                int r   = li >> 4;
                int c   = li & 15;
                int col = cg0 + c;
                if (col < N) {
                    size_t gi = (size_t)(rg0 + r) * N + col;
                    float v = patch[r * 20 + c] + bias[col];
                    if (MODE == 1) v = 0.5f * v * (1.0f + erff(v * 0.70710678118654752f));
                    if (MODE == 2) v += res[gi];
                    stval(C, gi, v);
                }
            }
            __syncwarp();
        }
}

// smem bytes for a config
#define GSMEM(BM_, BN_, BK_) (2 * ((BM_) * ((BK_) + 8) + (BK_) * ((BN_) + 8)) * 2)

// ---------------- fused flash attention ----------------
// One CTA = (b, h, 64-row q tile). 4 warps. qkv fp16 in, O fp16 out.
#define ATT_SMEM (4 * 64 * 72 * 2 + 2 * 64 * 68 * 4 + 2 * 64 * 4)

__global__ __launch_bounds__(128) void fattn_k(const __half* __restrict__ qkv,
                                               __half* __restrict__ o) {
    int bh = blockIdx.y;
    int b  = bh >> 3;
    int h  = bh & 7;
    int q0 = blockIdx.x << 6;
    int tid = threadIdx.x, warp = tid >> 5, lane = tid & 31;

    extern __shared__ char smem[];
    __half* Qs = (__half*)smem;             // 64*72
    __half* Ks = Qs + 64 * 72;
    __half* Vs = Ks + 64 * 72;
    __half* Ph = Vs + 64 * 72;
    float*  Sf = (float*)(Ph + 64 * 72);    // 64*68
    float*  Of = Sf + 64 * 68;
    float*  mrow = Of + 64 * 68;
    float*  lrow = mrow + 64;

    const uint32_t sQ = (uint32_t)__cvta_generic_to_shared(Qs);
    const uint32_t sK = (uint32_t)__cvta_generic_to_shared(Ks);
    const uint32_t sV = (uint32_t)__cvta_generic_to_shared(Vs);

    #pragma unroll
    for (int i = 0; i < 4; i++) {
        int idx = tid + i * 128;
        int r = idx >> 3, c = (idx & 7) * 8;
        uint32_t dst = sQ + (uint32_t)(r * 72 + c) * 2u;
        const __half* src = qkv + ((size_t)(b * TN + q0 + r)) * 1536 + h * 64 + c;
        asm volatile("cp.async.cg.shared.global [%0], [%1], 16;" :: "r"(dst), "l"(src));
    }
    asm volatile("cp.async.commit_group;" ::: "memory");

    for (int i = tid; i < 64 * 68; i += 128) Of[i] = 0.0f;
    if (tid < 64) { mrow[tid] = -1e30f; lrow[tid] = 0.0f; }

    const int jmax = q0 >> 6;
    for (int j = 0; j <= jmax; j++) {
        const int j0 = j << 6;
        #pragma unroll
        for (int i = 0; i < 4; i++) {
            int idx = tid + i * 128;
            int r = idx >> 3, c = (idx & 7) * 8;
            const __half* srcK = qkv + ((size_t)(b * TN + j0 + r)) * 1536 + 512 + h * 64 + c;
            const __half* srcV = qkv + ((size_t)(b * TN + j0 + r)) * 1536 + 1024 + h * 64 + c;
            uint32_t dK = sK + (uint32_t)(r * 72 + c) * 2u;
            uint32_t dV = sV + (uint32_t)(r * 72 + c) * 2u;
            asm volatile("cp.async.cg.shared.global [%0], [%1], 16;" :: "r"(dK), "l"(srcK));
            asm volatile("cp.async.cg.shared.global [%0], [%1], 16;" :: "r"(dV), "l"(srcV));
        }
        asm volatile("cp.async.commit_group;" ::: "memory");
        asm volatile("cp.async.wait_group 0;" ::: "memory");
        __syncthreads();

        // S = Q @ K^T (fp32 acc), warp w -> rows [w*16, w*16+16)
        {
            wmma::fragment<wmma::matrix_a, 16, 16, 16, __half, wmma::row_major> af;
            wmma::fragment<wmma::matrix_b, 16, 16, 16, __half, wmma::col_major> bf;
            wmma::fragment<wmma::accumulator, 16, 16, 16, float> ac[4];
            #pragma unroll
            for (int n = 0; n < 4; n++) wmma::fill_fragment(ac[n], 0.0f);
            #pragma unroll
            for (int k = 0; k < 4; k++) {
                wmma::load_matrix_sync(af, Qs + (warp * 16) * 72 + k * 16, 72);
                #pragma unroll
                for (int n = 0; n < 4; n++) {
                    wmma::load_matrix_sync(bf, Ks + (n * 16) * 72 + k * 16, 72);
                    wmma::mma_sync(ac[n], af, bf, ac[n]);
                }
            }
            #pragma unroll
            for (int n = 0; n < 4; n++)
                wmma::store_matrix_sync(Sf + (warp * 16) * 68 + n * 16, ac[n], 68,
                                        wmma::mem_row_major);
        }
        __syncthreads();

        // online softmax: 2 threads per row
        {
            int r  = tid >> 1;
            int hc = (tid & 1) * 32;
            bool diag = (j == jmax);
            float* srow = Sf + r * 68 + hc;
            float sv[32];
            float lm = -1e30f;
            #pragma unroll
            for (int c = 0; c < 32; c++) {
                float s = srow[c] * 0.125f;
                if (diag && (hc + c) > r) s = -1e30f;
                sv[c] = s;
                lm = fmaxf(lm, s);
            }
            float mt = fmaxf(lm, __shfl_xor_sync(0xffffffffu, lm, 1));
            float mo = mrow[r];
            float mn = fmaxf(mo, mt);
            float fs = expf(mo - mn);
            float sum = 0.0f;
            __half* prow = Ph + r * 72 + hc;
            #pragma unroll
            for (int c = 0; c < 32; c++) {
                float p = expf(sv[c] - mn);
                prow[c] = __float2half(p);
                sum += p;
            }
            sum += __shfl_xor_sync(0xffffffffu, sum, 1);
            float* orow = Of + r * 68 + hc;
            #pragma unroll
            for (int c = 0; c < 32; c++) orow[c] *= fs;
            __syncwarp();
            if ((tid & 1) == 0) {
                mrow[r] = mn;
                lrow[r] = lrow[r] * fs + sum;
            }
        }
        __syncthreads();

        // O += P @ V
        {
            wmma::fragment<wmma::matrix_a, 16, 16, 16, __half, wmma::row_major> af;
            wmma::fragment<wmma::matrix_b, 16, 16, 16, __half, wmma::row_major> bf;
            wmma::fragment<wmma::accumulator, 16, 16, 16, float> ac;
            #pragma unroll
            for (int n = 0; n < 4; n++) {
                wmma::load_matrix_sync(ac, Of + (warp * 16) * 68 + n * 16, 68,
                                       wmma::mem_row_major);
                #pragma unroll
                for (int k = 0; k < 4; k++) {
                    wmma::load_matrix_sync(af, Ph + (warp * 16) * 72 + k * 16, 72);
                    wmma::load_matrix_sync(bf, Vs + (k * 16) * 72 + n * 16, 72);
                    wmma::mma_sync(ac, af, bf, ac);
                }
                wmma::store_matrix_sync(Of + (warp * 16) * 68 + n * 16, ac, 68,
                                        wmma::mem_row_major);
            }
        }
        __syncthreads();
    }

    // epilogue: O / l -> fp16
    {
        int r  = tid >> 1;
        int hc = (tid & 1) * 32;
        float inv = 1.0f / lrow[r];
        float* orow = Of + r * 68 + hc;
        __half* dst = o + ((size_t)(b * TN + q0 + r)) * DM + h * 64 + hc;
        #pragma unroll
        for (int c = 0; c < 32; c++)
            dst[c] = __float2half(orow[c] * inv);
    }
}

// ---------------- launch ----------------
extern "C" void kernel_launch(void* const* d_in, const int* in_sizes, int n_in,
                              void* d_out, int out_size) {
    const int*   x      = (const int*)  d_in[0];
    const float* tok    = (const float*)d_in[1];
    const float* pos    = (const float*)d_in[2];
    const float* qkv_w  = (const float*)d_in[3];
    const float* qkv_b  = (const float*)d_in[4];
    const float* out_w  = (const float*)d_in[5];
    const float* out_b  = (const float*)d_in[6];
    const float* ln1_s  = (const float*)d_in[7];
    const float* ln1_b  = (const float*)d_in[8];
    const float* ff1_w  = (const float*)d_in[9];
    const float* ff1_b  = (const float*)d_in[10];
    const float* ff2_w  = (const float*)d_in[11];
    const float* ff2_b  = (const float*)d_in[12];
    const float* ln2_s  = (const float*)d_in[13];
    const float* ln2_b  = (const float*)d_in[14];
    const float* lnf_s  = (const float*)d_in[15];
    const float* lnf_b  = (const float*)d_in[16];
    const float* head_w = (const float*)d_in[17];
    const float* head_b = (const float*)d_in[18];
    float* out = (float*)d_out;

    float *h;
    __half *tmpH, *qkvA, *attH, *ffH, *qkvH, *outH, *ff1H, *ff2H, *headH;
    cudaGetSymbolAddress((void**)&h,    g_h);
    cudaGetSymbolAddress((void**)&tmpH, g_tmpH);
    cudaGetSymbolAddress((void**)&qkvA, g_qkvA);
    cudaGetSymbolAddress((void**)&attH, g_attH);
    cudaGetSymbolAddress((void**)&ffH,  g_ffH);
    cudaGetSymbolAddress((void**)&qkvH, g_qkvH);
    cudaGetSymbolAddress((void**)&outH, g_outH);
    cudaGetSymbolAddress((void**)&ff1H, g_ff1H);
    cudaGetSymbolAddress((void**)&ff2H, g_ff2H);
    cudaGetSymbolAddress((void**)&headH,g_headH);

    const int M = BS * TN;  // 2048
    const int SMBIG = GSMEM(128, 128, 64);   // 71680 B
    const int SMSML = GSMEM(64, 64, 32);     // 19456 B

    cudaFuncSetAttribute(gemmh<128,128,64,128,2,2,0,__half>, cudaFuncAttributeMaxDynamicSharedMemorySize, SMBIG);
    cudaFuncSetAttribute(gemmh<128,128,64,128,2,2,1,__half>, cudaFuncAttributeMaxDynamicSharedMemorySize, SMBIG);
    cudaFuncSetAttribute(gemmh<128,128,64,128,2,2,0,float>,  cudaFuncAttributeMaxDynamicSharedMemorySize, SMBIG);
    cudaFuncSetAttribute(fattn_k, cudaFuncAttributeMaxDynamicSharedMemorySize, ATT_SMEM);

    // weight conversions (fp32 -> fp16), 4 elems/thread
    {
        int n4;
        n4 = LN_*DM*3*DM/4;  convh_k<<<(n4+255)/256, 256>>>(qkv_w, qkvH, n4);
        n4 = LN_*DM*DM/4;    convh_k<<<(n4+255)/256, 256>>>(out_w, outH, n4);
        n4 = LN_*DM*4*DM/4;  convh_k<<<(n4+255)/256, 256>>>(ff1_w, ff1H, n4);
        n4 = LN_*4*DM*DM/4;  convh_k<<<(n4+255)/256, 256>>>(ff2_w, ff2H, n4);
        convpad_k<<<dim3((VNP/4+255)/256, DM), 256>>>(head_w, headH);
    }

    embed_k<<<(BS*TN*DM + 255) / 256, 256>>>(x, tok, pos, h);

    for (int l = 0; l < LN_; l++) {
        const __half* wq = qkvH + (size_t)l * DM * 3*DM;
        const __half* wo = outH + (size_t)l * DM * DM;
        const __half* w1 = ff1H + (size_t)l * DM * 4*DM;
        const __half* w2 = ff2H + (size_t)l * 4*DM * DM;
        const float* bq = qkv_b + (size_t)l * 3*DM;
        const float* bo = out_b + (size_t)l * DM;
        const float* b1 = ff1_b + (size_t)l * 4*DM;
        const float* b2 = ff2_b + (size_t)l * DM;

        // attention block
        ln_k<<<M / 8, 256>>>(h, tmpH, ln1_s + l * DM, ln1_b + l * DM);
        gemmh<128,128,64,128,2,2,0,__half><<<dim3(16, 12), 128, SMBIG>>>(tmpH, wq, bq, nullptr, qkvA, M, 3*DM, DM, 3*DM);
        fattn_k<<<dim3(8, 32), 128, ATT_SMEM>>>(qkvA, attH);
        gemmh<64,64,32,128,2,2,2,float><<<dim3(32, 8), 128, SMSML>>>(attH, wo, bo, h, h, M, DM, DM, DM);

        // feed-forward block
        ln_k<<<M / 8, 256>>>(h, tmpH, ln2_s + l * DM, ln2_b + l * DM);
        gemmh<128,128,64,128,2,2,1,__half><<<dim3(16, 16), 128, SMBIG>>>(tmpH, w1, b1, nullptr, ffH, M, 4*DM, DM, 4*DM);
        gemmh<64,64,32,128,2,2,2,float><<<dim3(32, 8), 128, SMSML>>>(ffH, w2, b2, h, h, M, DM, 4*DM, DM);
    }

    // final LN + LM head
    ln_k<<<M / 8, 256>>>(h, tmpH, lnf_s, lnf_b);
    gemmh<128,128,64,128,2,2,0,float><<<dim3(16, VNP / 128), 128, SMBIG>>>(tmpH, headH, head_b, nullptr, out, M, VN, DM, VNP);
}

// round 15
// speedup vs baseline: 1.5113x; 1.4030x over previous
#include <cuda_runtime.h>
#include <cuda_fp16.h>
#include <mma.h>
#include <cstdint>

using namespace nvcuda;

#define BS   4
#define TN   512
#define DM   512
#define HN   8
#define HDN  64
#define LN_  6
#define VN   50257
#define VNP  50304          // VN padded to multiple of 128
#define EPSV 1e-5f

// ---------------- scratch ----------------
__device__ float  g_h   [BS*TN*DM];          // residual stream (fp32)
__device__ __half g_tmpH[BS*TN*DM];          // LN output (fp16, GEMM A)
__device__ __half g_qkvA[BS*TN*3*DM];        // qkv activations (fp16)
__device__ __half g_attH[BS*TN*DM];          // attention output (fp16, GEMM A)
__device__ __half g_ffH [BS*TN*4*DM];        // ff1 output (fp16, GEMM A)
// fp16 weights ([K,N] row-major)
__device__ __half g_qkvH[LN_*DM*3*DM];
__device__ __half g_outH[LN_*DM*DM];
__device__ __half g_ff1H[LN_*DM*4*DM];
__device__ __half g_ff2H[LN_*4*DM*DM];
__device__ __half g_headH[DM*VNP];           // zero-padded

// ---------------- weight conversion (vectorized: 4 elems/thread) ----------------
__global__ void convh_k(const float* __restrict__ src, __half* __restrict__ dst, int n4) {
    int i = blockIdx.x * 256 + threadIdx.x;
    if (i >= n4) return;
    float4 v = *(const float4*)&src[i * 4];
    __half2* d = (__half2*)&dst[i * 4];
    d[0] = __floats2half2_rn(v.x, v.y);
    d[1] = __floats2half2_rn(v.z, v.w);
}
__global__ void convpad_k(const float* __restrict__ src, __half* __restrict__ dst) {
    int n = (blockIdx.x * 256 + threadIdx.x) * 4;
    int k = blockIdx.y;
    if (n >= VNP) return;
    const float* sp = src + (size_t)k * VN;
    float a = (n + 0 < VN) ? sp[n + 0] : 0.0f;
    float b = (n + 1 < VN) ? sp[n + 1] : 0.0f;
    float c = (n + 2 < VN) ? sp[n + 2] : 0.0f;
    float d = (n + 3 < VN) ? sp[n + 3] : 0.0f;
    __half2* dp = (__half2*)&dst[(size_t)k * VNP + n];
    dp[0] = __floats2half2_rn(a, b);
    dp[1] = __floats2half2_rn(c, d);
}

// ---------------- embedding ----------------
__global__ void embed_k(const int* __restrict__ x, const float* __restrict__ tok,
                        const float* __restrict__ pos, float* __restrict__ h) {
    int i = blockIdx.x * 256 + threadIdx.x;
    if (i >= BS*TN*DM) return;
    int d  = i % DM;
    int bt = i / DM;
    int t  = bt % TN;
    h[i] = tok[(size_t)x[bt] * DM + d] + pos[t * DM + d];
}

// ---------------- layernorm: warp per row, 8 rows/CTA ----------------
__global__ __launch_bounds__(256) void ln_k(const float* __restrict__ in, __half* __restrict__ out,
                                            const float* __restrict__ sc, const float* __restrict__ bi) {
    int warp = threadIdx.x >> 5, lane = threadIdx.x & 31;
    int row = blockIdx.x * 8 + warp;
    const float4* xr = (const float4*)(in + (size_t)row * DM);
    float4 v[4];
    float s1 = 0.0f, s2 = 0.0f;
    #pragma unroll
    for (int i = 0; i < 4; i++) {
        v[i] = xr[lane + i * 32];
        s1 += v[i].x + v[i].y + v[i].z + v[i].w;
        s2 += v[i].x*v[i].x + v[i].y*v[i].y + v[i].z*v[i].z + v[i].w*v[i].w;
    }
    #pragma unroll
    for (int o = 16; o; o >>= 1) {
        s1 += __shfl_xor_sync(0xffffffffu, s1, o);
        s2 += __shfl_xor_sync(0xffffffffu, s2, o);
    }
    float mean = s1 * (1.0f / DM);
    float r = rsqrtf(s2 * (1.0f / DM) - mean * mean + EPSV);
    const float4* sc4 = (const float4*)sc;
    const float4* bi4 = (const float4*)bi;
    __half2* op = (__half2*)(out + (size_t)row * DM);
    #pragma unroll
    for (int i = 0; i < 4; i++) {
        int ch = lane + i * 32;
        float4 g = sc4[ch], bb = bi4[ch];
        float4 x = v[i];
        op[ch * 2]     = __floats2half2_rn((x.x - mean) * r * g.x + bb.x,
                                           (x.y - mean) * r * g.y + bb.y);
        op[ch * 2 + 1] = __floats2half2_rn((x.z - mean) * r * g.z + bb.z,
                                           (x.w - mean) * r * g.w + bb.w);
    }
}

// ---------------- epilogue store helpers ----------------
__device__ __forceinline__ void stval(float* C, size_t i, float v)  { C[i] = v; }
__device__ __forceinline__ void stval(__half* C, size_t i, float v) { C[i] = __float2half(v); }

// ---------------- fp16 wmma GEMM, 2-stage cp.async, dynamic smem ----------------
// C[M,N] = A[M,K](fp16) @ B[K,N](fp16) + bias (+epilogue), fp32 accumulate.
// MODE 0: bias; 1: bias + exact gelu; 2: bias + residual.
// Bs = B row stride (>= N, multiple of 8). 16B-aligned cp.async by construction.
template <int BM, int BN, int BK, int NT, int WR, int WC, int MODE, typename OT>
__global__ __launch_bounds__(NT) void gemmh(const __half* __restrict__ A,
                                            const __half* __restrict__ B,
                                            const float* __restrict__ bias,
                                            const float* __restrict__ res,
                                            OT* __restrict__ C,
                                            int M, int N, int K, int Bs) {
    constexpr int LDA = BK + 8;
    constexpr int LDB = BN + 8;
    constexpr int WTM = BM / WR;
    constexpr int WTN = BN / WC;
    constexpr int FM  = WTM / 16;
    constexpr int FN  = WTN / 16;
    constexpr int CHA = BK / 8;               // 16B chunks per A row
    constexpr int CHB = BN / 8;               // 16B chunks per B row
    constexpr int IA  = (BM * CHA) / NT;
    constexpr int IB  = (BK * CHB) / NT;
    constexpr int SZA = BM * LDA;             // halves per A stage
    constexpr int SZB = BK * LDB;             // halves per B stage

    extern __shared__ char dsm[];
    __half* smA = (__half*)dsm;
    __half* smB = smA + 2 * SZA;

    const int tid  = threadIdx.x;
    const int warp = tid >> 5;
    const int lane = tid & 31;
    const int wm   = warp / WC;
    const int wn   = warp % WC;
    const int m0   = blockIdx.x * BM;
    const int n0   = blockIdx.y * BN;

    const uint32_t sA0 = (uint32_t)__cvta_generic_to_shared(smA);
    const uint32_t sB0 = (uint32_t)__cvta_generic_to_shared(smB);

    wmma::fragment<wmma::accumulator, 16, 16, 16, float> acc[FM][FN];
    #pragma unroll
    for (int i = 0; i < FM; i++)
        #pragma unroll
        for (int j = 0; j < FN; j++)
            wmma::fill_fragment(acc[i][j], 0.0f);

    auto issue = [&](int buf, int k0) {
        #pragma unroll
        for (int i = 0; i < IA; i++) {
            int idx = tid + i * NT;
            int r = idx / CHA, c = (idx % CHA) * 8;
            uint32_t dst = sA0 + (uint32_t)(buf * SZA + r * LDA + c) * 2u;
            const __half* src = A + (size_t)(m0 + r) * K + k0 + c;
            asm volatile("cp.async.cg.shared.global [%0], [%1], 16;" :: "r"(dst), "l"(src));
        }
        #pragma unroll
        for (int i = 0; i < IB; i++) {
            int idx = tid + i * NT;
            int r = idx / CHB, c = (idx % CHB) * 8;
            uint32_t dst = sB0 + (uint32_t)(buf * SZB + r * LDB + c) * 2u;
            const __half* src = B + (size_t)(k0 + r) * Bs + n0 + c;
            asm volatile("cp.async.cg.shared.global [%0], [%1], 16;" :: "r"(dst), "l"(src));
        }
    };

    const int nst = K / BK;

    issue(0, 0);
    asm volatile("cp.async.commit_group;" ::: "memory");

    for (int s = 0; s < nst; s++) {
        if (s + 1 < nst) {
            issue((s + 1) & 1, (s + 1) * BK);
            asm volatile("cp.async.commit_group;" ::: "memory");
            asm volatile("cp.async.wait_group 1;" ::: "memory");
        } else {
            asm volatile("cp.async.wait_group 0;" ::: "memory");
        }
        __syncthreads();

        const int buf = s & 1;
        const __half* pa = smA + buf * SZA;
        const __half* pb = smB + buf * SZB;
        #pragma unroll
        for (int ks = 0; ks < BK; ks += 16) {
            wmma::fragment<wmma::matrix_a, 16, 16, 16, __half, wmma::row_major> af[FM];
            wmma::fragment<wmma::matrix_b, 16, 16, 16, __half, wmma::row_major> bf[FN];
            #pragma unroll
            for (int i = 0; i < FM; i++)
                wmma::load_matrix_sync(af[i], pa + (wm * WTM + i * 16) * LDA + ks, LDA);
            #pragma unroll
            for (int j = 0; j < FN; j++)
                wmma::load_matrix_sync(bf[j], pb + ks * LDB + wn * WTN + j * 16, LDB);
            #pragma unroll
            for (int i = 0; i < FM; i++)
                #pragma unroll
                for (int j = 0; j < FN; j++)
                    wmma::mma_sync(acc[i][j], af[i], bf[j], acc[i][j]);
        }
        __syncthreads();
    }

    // fused epilogue via per-warp smem patch (pipeline smem is dead)
    // Coalesced mapping: li = e*32 + lane -> lane-consecutive columns.
    float* patch = (float*)dsm + warp * (16 * 20);
    #pragma unroll
    for (int i = 0; i < FM; i++)
        #pragma unroll
        for (int j = 0; j < FN; j++) {
            wmma::store_matrix_sync(patch, acc[i][j], 20, wmma::mem_row_major);
            __syncwarp();
            const int rg0 = m0 + wm * WTM + i * 16;
            const int cg0 = n0 + wn * WTN + j * 16;
            #pragma unroll
            for (int e = 0; e < 8; e++) {
                int li  = e * 32 + lane;
                int r   = li >> 4;
                int c   = li & 15;
                int col = cg0 + c;
                if (col < N) {
                    size_t gi = (size_t)(rg0 + r) * N + col;
                    float v = patch[r * 20 + c] + bias[col];
                    if (MODE == 1) v = 0.5f * v * (1.0f + erff(v * 0.70710678118654752f));
                    if (MODE == 2) v += res[gi];
                    stval(C, gi, v);
                }
            }
            __syncwarp();
        }
}

// smem bytes for a config
#define GSMEM(BM_, BN_, BK_) (2 * ((BM_) * ((BK_) + 8) + (BK_) * ((BN_) + 8)) * 2)

// ---------------- fused flash attention ----------------
// One CTA = (b, h, 64-row q tile). 4 warps. qkv fp16 in, O fp16 out.
#define ATT_SMEM (4 * 64 * 72 * 2 + 2 * 64 * 68 * 4 + 2 * 64 * 4)

__global__ __launch_bounds__(128) void fattn_k(const __half* __restrict__ qkv,
                                               __half* __restrict__ o) {
    int bh = blockIdx.y;
    int b  = bh >> 3;
    int h  = bh & 7;
    int q0 = blockIdx.x << 6;
    int tid = threadIdx.x, warp = tid >> 5, lane = tid & 31;

    extern __shared__ char smem[];
    __half* Qs = (__half*)smem;             // 64*72
    __half* Ks = Qs + 64 * 72;
    __half* Vs = Ks + 64 * 72;
    __half* Ph = Vs + 64 * 72;
    float*  Sf = (float*)(Ph + 64 * 72);    // 64*68
    float*  Of = Sf + 64 * 68;
    float*  mrow = Of + 64 * 68;
    float*  lrow = mrow + 64;

    const uint32_t sQ = (uint32_t)__cvta_generic_to_shared(Qs);
    const uint32_t sK = (uint32_t)__cvta_generic_to_shared(Ks);
    const uint32_t sV = (uint32_t)__cvta_generic_to_shared(Vs);

    #pragma unroll
    for (int i = 0; i < 4; i++) {
        int idx = tid + i * 128;
        int r = idx >> 3, c = (idx & 7) * 8;
        uint32_t dst = sQ + (uint32_t)(r * 72 + c) * 2u;
        const __half* src = qkv + ((size_t)(b * TN + q0 + r)) * 1536 + h * 64 + c;
        asm volatile("cp.async.cg.shared.global [%0], [%1], 16;" :: "r"(dst), "l"(src));
    }
    asm volatile("cp.async.commit_group;" ::: "memory");

    for (int i = tid; i < 64 * 68; i += 128) Of[i] = 0.0f;
    if (tid < 64) { mrow[tid] = -1e30f; lrow[tid] = 0.0f; }

    const int jmax = q0 >> 6;
    for (int j = 0; j <= jmax; j++) {
        const int j0 = j << 6;
        #pragma unroll
        for (int i = 0; i < 4; i++) {
            int idx = tid + i * 128;
            int r = idx >> 3, c = (idx & 7) * 8;
            const __half* srcK = qkv + ((size_t)(b * TN + j0 + r)) * 1536 + 512 + h * 64 + c;
            const __half* srcV = qkv + ((size_t)(b * TN + j0 + r)) * 1536 + 1024 + h * 64 + c;
            uint32_t dK = sK + (uint32_t)(r * 72 + c) * 2u;
            uint32_t dV = sV + (uint32_t)(r * 72 + c) * 2u;
            asm volatile("cp.async.cg.shared.global [%0], [%1], 16;" :: "r"(dK), "l"(srcK));
            asm volatile("cp.async.cg.shared.global [%0], [%1], 16;" :: "r"(dV), "l"(srcV));
        }
        asm volatile("cp.async.commit_group;" ::: "memory");
        asm volatile("cp.async.wait_group 0;" ::: "memory");
        __syncthreads();

        // S = Q @ K^T (fp32 acc), warp w -> rows [w*16, w*16+16)
        {
            wmma::fragment<wmma::matrix_a, 16, 16, 16, __half, wmma::row_major> af;
            wmma::fragment<wmma::matrix_b, 16, 16, 16, __half, wmma::col_major> bf;
            wmma::fragment<wmma::accumulator, 16, 16, 16, float> ac[4];
            #pragma unroll
            for (int n = 0; n < 4; n++) wmma::fill_fragment(ac[n], 0.0f);
            #pragma unroll
            for (int k = 0; k < 4; k++) {
                wmma::load_matrix_sync(af, Qs + (warp * 16) * 72 + k * 16, 72);
                #pragma unroll
                for (int n = 0; n < 4; n++) {
                    wmma::load_matrix_sync(bf, Ks + (n * 16) * 72 + k * 16, 72);
                    wmma::mma_sync(ac[n], af, bf, ac[n]);
                }
            }
            #pragma unroll
            for (int n = 0; n < 4; n++)
                wmma::store_matrix_sync(Sf + (warp * 16) * 68 + n * 16, ac[n], 68,
                                        wmma::mem_row_major);
        }
        __syncthreads();

        // online softmax: 2 threads per row
        {
            int r  = tid >> 1;
            int hc = (tid & 1) * 32;
            bool diag = (j == jmax);
            float* srow = Sf + r * 68 + hc;
            float sv[32];
            float lm = -1e30f;
            #pragma unroll
            for (int c = 0; c < 32; c++) {
                float s = srow[c] * 0.125f;
                if (diag && (hc + c) > r) s = -1e30f;
                sv[c] = s;
                lm = fmaxf(lm, s);
            }
            float mt = fmaxf(lm, __shfl_xor_sync(0xffffffffu, lm, 1));
            float mo = mrow[r];
            float mn = fmaxf(mo, mt);
            float fs = expf(mo - mn);
            float sum = 0.0f;
            __half* prow = Ph + r * 72 + hc;
            #pragma unroll
            for (int c = 0; c < 32; c++) {
                float p = expf(sv[c] - mn);
                prow[c] = __float2half(p);
                sum += p;
            }
            sum += __shfl_xor_sync(0xffffffffu, sum, 1);
            float* orow = Of + r * 68 + hc;
            #pragma unroll
            for (int c = 0; c < 32; c++) orow[c] *= fs;
            __syncwarp();
            if ((tid & 1) == 0) {
                mrow[r] = mn;
                lrow[r] = lrow[r] * fs + sum;
            }
        }
        __syncthreads();

        // O += P @ V
        {
            wmma::fragment<wmma::matrix_a, 16, 16, 16, __half, wmma::row_major> af;
            wmma::fragment<wmma::matrix_b, 16, 16, 16, __half, wmma::row_major> bf;
            wmma::fragment<wmma::accumulator, 16, 16, 16, float> ac;
            #pragma unroll
            for (int n = 0; n < 4; n++) {
                wmma::load_matrix_sync(ac, Of + (warp * 16) * 68 + n * 16, 68,
                                       wmma::mem_row_major);
                #pragma unroll
                for (int k = 0; k < 4; k++) {
                    wmma::load_matrix_sync(af, Ph + (warp * 16) * 72 + k * 16, 72);
                    wmma::load_matrix_sync(bf, Vs + (k * 16) * 72 + n * 16, 72);
                    wmma::mma_sync(ac, af, bf, ac);
                }
                wmma::store_matrix_sync(Of + (warp * 16) * 68 + n * 16, ac, 68,
                                        wmma::mem_row_major);
            }
        }
        __syncthreads();
    }

    // epilogue: O / l -> fp16, coalesced 16B stores (same chunking as loads)
    #pragma unroll
    for (int i = 0; i < 4; i++) {
        int idx = tid + i * 128;
        int r = idx >> 3, c0 = (idx & 7) * 8;
        float inv = 1.0f / lrow[r];
        const float* orow = Of + r * 68 + c0;
        __half2 hv[4];
        #pragma unroll
        for (int k = 0; k < 4; k++)
            hv[k] = __halves2half2(__float2half(orow[k * 2] * inv),
                                   __float2half(orow[k * 2 + 1] * inv));
        *(uint4*)(o + ((size_t)(b * TN + q0 + r)) * DM + h * 64 + c0) = *(uint4*)hv;
    }
}

// ---------------- launch ----------------
extern "C" void kernel_launch(void* const* d_in, const int* in_sizes, int n_in,
                              void* d_out, int out_size) {
    const int*   x      = (const int*)  d_in[0];
    const float* tok    = (const float*)d_in[1];
    const float* pos    = (const float*)d_in[2];
    const float* qkv_w  = (const float*)d_in[3];
    const float* qkv_b  = (const float*)d_in[4];
    const float* out_w  = (const float*)d_in[5];
    const float* out_b  = (const float*)d_in[6];
    const float* ln1_s  = (const float*)d_in[7];
    const float* ln1_b  = (const float*)d_in[8];
    const float* ff1_w  = (const float*)d_in[9];
    const float* ff1_b  = (const float*)d_in[10];
    const float* ff2_w  = (const float*)d_in[11];
    const float* ff2_b  = (const float*)d_in[12];
    const float* ln2_s  = (const float*)d_in[13];
    const float* ln2_b  = (const float*)d_in[14];
    const float* lnf_s  = (const float*)d_in[15];
    const float* lnf_b  = (const float*)d_in[16];
    const float* head_w = (const float*)d_in[17];
    const float* head_b = (const float*)d_in[18];
    float* out = (float*)d_out;

    float *h;
    __half *tmpH, *qkvA, *attH, *ffH, *qkvH, *outH, *ff1H, *ff2H, *headH;
    cudaGetSymbolAddress((void**)&h,    g_h);
    cudaGetSymbolAddress((void**)&tmpH, g_tmpH);
    cudaGetSymbolAddress((void**)&qkvA, g_qkvA);
    cudaGetSymbolAddress((void**)&attH, g_attH);
    cudaGetSymbolAddress((void**)&ffH,  g_ffH);
    cudaGetSymbolAddress((void**)&qkvH, g_qkvH);
    cudaGetSymbolAddress((void**)&outH, g_outH);
    cudaGetSymbolAddress((void**)&ff1H, g_ff1H);
    cudaGetSymbolAddress((void**)&ff2H, g_ff2H);
    cudaGetSymbolAddress((void**)&headH,g_headH);

    const int M = BS * TN;  // 2048
    const int SMBIG = GSMEM(128, 128, 64);   // 71680 B
    const int SMSML = GSMEM(64, 64, 32);     // 19456 B

    cudaFuncSetAttribute(gemmh<128,128,64,128,2,2,0,__half>, cudaFuncAttributeMaxDynamicSharedMemorySize, SMBIG);
    cudaFuncSetAttribute(gemmh<128,128,64,128,2,2,1,__half>, cudaFuncAttributeMaxDynamicSharedMemorySize, SMBIG);
    cudaFuncSetAttribute(gemmh<128,128,64,128,2,2,0,float>,  cudaFuncAttributeMaxDynamicSharedMemorySize, SMBIG);
    cudaFuncSetAttribute(fattn_k, cudaFuncAttributeMaxDynamicSharedMemorySize, ATT_SMEM);

    // weight conversions (fp32 -> fp16), 4 elems/thread
    {
        int n4;
        n4 = LN_*DM*3*DM/4;  convh_k<<<(n4+255)/256, 256>>>(qkv_w, qkvH, n4);
        n4 = LN_*DM*DM/4;    convh_k<<<(n4+255)/256, 256>>>(out_w, outH, n4);
        n4 = LN_*DM*4*DM/4;  convh_k<<<(n4+255)/256, 256>>>(ff1_w, ff1H, n4);
        n4 = LN_*4*DM*DM/4;  convh_k<<<(n4+255)/256, 256>>>(ff2_w, ff2H, n4);
        convpad_k<<<dim3((VNP/4+255)/256, DM), 256>>>(head_w, headH);
    }

    embed_k<<<(BS*TN*DM + 255) / 256, 256>>>(x, tok, pos, h);

    for (int l = 0; l < LN_; l++) {
        const __half* wq = qkvH + (size_t)l * DM * 3*DM;
        const __half* wo = outH + (size_t)l * DM * DM;
        const __half* w1 = ff1H + (size_t)l * DM * 4*DM;
        const __half* w2 = ff2H + (size_t)l * 4*DM * DM;
        const float* bq = qkv_b + (size_t)l * 3*DM;
        const float* bo = out_b + (size_t)l * DM;
        const float* b1 = ff1_b + (size_t)l * 4*DM;
        const float* b2 = ff2_b + (size_t)l * DM;

        // attention block
        ln_k<<<M / 8, 256>>>(h, tmpH, ln1_s + l * DM, ln1_b + l * DM);
        gemmh<128,128,64,128,2,2,0,__half><<<dim3(16, 12), 128, SMBIG>>>(tmpH, wq, bq, nullptr, qkvA, M, 3*DM, DM, 3*DM);
        fattn_k<<<dim3(8, 32), 128, ATT_SMEM>>>(qkvA, attH);
        gemmh<64,64,32,128,2,2,2,float><<<dim3(32, 8), 128, SMSML>>>(attH, wo, bo, h, h, M, DM, DM, DM);

        // feed-forward block
        ln_k<<<M / 8, 256>>>(h, tmpH, ln2_s + l * DM, ln2_b + l * DM);
        gemmh<128,128,64,128,2,2,1,__half><<<dim3(16, 16), 128, SMBIG>>>(tmpH, w1, b1, nullptr, ffH, M, 4*DM, DM, 4*DM);
        gemmh<64,64,32,128,2,2,2,float><<<dim3(32, 8), 128, SMSML>>>(ffH, w2, b2, h, h, M, DM, 4*DM, DM);
    }

    // final LN + LM head
    ln_k<<<M / 8, 256>>>(h, tmpH, lnf_s, lnf_b);
    gemmh<128,128,64,128,2,2,0,float><<<dim3(16, VNP / 128), 128, SMBIG>>>(tmpH, headH, head_b, nullptr, out, M, VN, DM, VNP);
}

// round 16
// speedup vs baseline: 1.6472x; 1.0900x over previous
#include <cuda_runtime.h>
#include <cuda_fp16.h>
#include <mma.h>
#include <cstdint>

using namespace nvcuda;

#define BS   4
#define TN   512
#define DM   512
#define HN   8
#define HDN  64
#define LN_  6
#define VN   50257
#define VNP  50304          // VN padded to multiple of 128
#define EPSV 1e-5f

// ---------------- scratch ----------------
__device__ float  g_h   [BS*TN*DM];          // residual stream (fp32)
__device__ __half g_tmpH[BS*TN*DM];          // LN output (fp16, GEMM A)
__device__ __half g_qkvA[BS*TN*3*DM];        // qkv activations (fp16)
__device__ __half g_attH[BS*TN*DM];          // attention output (fp16, GEMM A)
__device__ __half g_ffH [BS*TN*4*DM];        // ff1 output (fp16, GEMM A)
// fp16 weights ([K,N] row-major)
__device__ __half g_qkvH[LN_*DM*3*DM];
__device__ __half g_outH[LN_*DM*DM];
__device__ __half g_ff1H[LN_*DM*4*DM];
__device__ __half g_ff2H[LN_*4*DM*DM];
__device__ __half g_headH[DM*VNP];           // zero-padded

// ---------------- weight conversion (vectorized: 4 elems/thread) ----------------
__global__ void convh_k(const float* __restrict__ src, __half* __restrict__ dst, int n4) {
    int i = blockIdx.x * 256 + threadIdx.x;
    if (i >= n4) return;
    float4 v = *(const float4*)&src[i * 4];
    __half2* d = (__half2*)&dst[i * 4];
    d[0] = __floats2half2_rn(v.x, v.y);
    d[1] = __floats2half2_rn(v.z, v.w);
}
__global__ void convpad_k(const float* __restrict__ src, __half* __restrict__ dst) {
    int n = (blockIdx.x * 256 + threadIdx.x) * 4;
    int k = blockIdx.y;
    if (n >= VNP) return;
    const float* sp = src + (size_t)k * VN;
    float a = (n + 0 < VN) ? sp[n + 0] : 0.0f;
    float b = (n + 1 < VN) ? sp[n + 1] : 0.0f;
    float c = (n + 2 < VN) ? sp[n + 2] : 0.0f;
    float d = (n + 3 < VN) ? sp[n + 3] : 0.0f;
    __half2* dp = (__half2*)&dst[(size_t)k * VNP + n];
    dp[0] = __floats2half2_rn(a, b);
    dp[1] = __floats2half2_rn(c, d);
}

// ---------------- embedding ----------------
__global__ void embed_k(const int* __restrict__ x, const float* __restrict__ tok,
                        const float* __restrict__ pos, float* __restrict__ h) {
    int i = blockIdx.x * 256 + threadIdx.x;
    if (i >= BS*TN*DM) return;
    int d  = i % DM;
    int bt = i / DM;
    int t  = bt % TN;
    h[i] = tok[(size_t)x[bt] * DM + d] + pos[t * DM + d];
}

// ---------------- layernorm: warp per row, 8 rows/CTA ----------------
__global__ __launch_bounds__(256) void ln_k(const float* __restrict__ in, __half* __restrict__ out,
                                            const float* __restrict__ sc, const float* __restrict__ bi) {
    int warp = threadIdx.x >> 5, lane = threadIdx.x & 31;
    int row = blockIdx.x * 8 + warp;
    const float4* xr = (const float4*)(in + (size_t)row * DM);
    float4 v[4];
    float s1 = 0.0f, s2 = 0.0f;
    #pragma unroll
    for (int i = 0; i < 4; i++) {
        v[i] = xr[lane + i * 32];
        s1 += v[i].x + v[i].y + v[i].z + v[i].w;
        s2 += v[i].x*v[i].x + v[i].y*v[i].y + v[i].z*v[i].z + v[i].w*v[i].w;
    }
    #pragma unroll
    for (int o = 16; o; o >>= 1) {
        s1 += __shfl_xor_sync(0xffffffffu, s1, o);
        s2 += __shfl_xor_sync(0xffffffffu, s2, o);
    }
    float mean = s1 * (1.0f / DM);
    float r = rsqrtf(s2 * (1.0f / DM) - mean * mean + EPSV);
    const float4* sc4 = (const float4*)sc;
    const float4* bi4 = (const float4*)bi;
    __half2* op = (__half2*)(out + (size_t)row * DM);
    #pragma unroll
    for (int i = 0; i < 4; i++) {
        int ch = lane + i * 32;
        float4 g = sc4[ch], bb = bi4[ch];
        float4 x = v[i];
        op[ch * 2]     = __floats2half2_rn((x.x - mean) * r * g.x + bb.x,
                                           (x.y - mean) * r * g.y + bb.y);
        op[ch * 2 + 1] = __floats2half2_rn((x.z - mean) * r * g.z + bb.z,
                                           (x.w - mean) * r * g.w + bb.w);
    }
}

// ---------------- epilogue store helpers ----------------
__device__ __forceinline__ void stval(float* C, size_t i, float v)  { C[i] = v; }
__device__ __forceinline__ void stval(__half* C, size_t i, float v) { C[i] = __float2half(v); }

// ---------------- fp16 wmma GEMM, 2-stage cp.async, dynamic smem ----------------
// C[M,N] = A[M,K](fp16) @ B[K,N](fp16) + bias (+epilogue), fp32 accumulate.
// MODE 0: bias; 1: bias + exact gelu; 2: bias + residual.
// Bs = B row stride (>= N, multiple of 8). 16B-aligned cp.async by construction.
template <int BM, int BN, int BK, int NT, int WR, int WC, int MODE, typename OT>
__global__ __launch_bounds__(NT) void gemmh(const __half* __restrict__ A,
                                            const __half* __restrict__ B,
                                            const float* __restrict__ bias,
                                            const float* __restrict__ res,
                                            OT* __restrict__ C,
                                            int M, int N, int K, int Bs) {
    constexpr int LDA = BK + 8;
    constexpr int LDB = BN + 8;
    constexpr int WTM = BM / WR;
    constexpr int WTN = BN / WC;
    constexpr int FM  = WTM / 16;
    constexpr int FN  = WTN / 16;
    constexpr int CHA = BK / 8;               // 16B chunks per A row
    constexpr int CHB = BN / 8;               // 16B chunks per B row
    constexpr int IA  = (BM * CHA) / NT;
    constexpr int IB  = (BK * CHB) / NT;
    constexpr int SZA = BM * LDA;             // halves per A stage
    constexpr int SZB = BK * LDB;             // halves per B stage

    extern __shared__ char dsm[];
    __half* smA = (__half*)dsm;
    __half* smB = smA + 2 * SZA;

    const int tid  = threadIdx.x;
    const int warp = tid >> 5;
    const int lane = tid & 31;
    const int wm   = warp / WC;
    const int wn   = warp % WC;
    const int m0   = blockIdx.x * BM;
    const int n0   = blockIdx.y * BN;

    const uint32_t sA0 = (uint32_t)__cvta_generic_to_shared(smA);
    const uint32_t sB0 = (uint32_t)__cvta_generic_to_shared(smB);

    wmma::fragment<wmma::accumulator, 16, 16, 16, float> acc[FM][FN];
    #pragma unroll
    for (int i = 0; i < FM; i++)
        #pragma unroll
        for (int j = 0; j < FN; j++)
            wmma::fill_fragment(acc[i][j], 0.0f);

    auto issue = [&](int buf, int k0) {
        #pragma unroll
        for (int i = 0; i < IA; i++) {
            int idx = tid + i * NT;
            int r = idx / CHA, c = (idx % CHA) * 8;
            uint32_t dst = sA0 + (uint32_t)(buf * SZA + r * LDA + c) * 2u;
            const __half* src = A + (size_t)(m0 + r) * K + k0 + c;
            asm volatile("cp.async.cg.shared.global [%0], [%1], 16;" :: "r"(dst), "l"(src));
        }
        #pragma unroll
        for (int i = 0; i < IB; i++) {
            int idx = tid + i * NT;
            int r = idx / CHB, c = (idx % CHB) * 8;
            uint32_t dst = sB0 + (uint32_t)(buf * SZB + r * LDB + c) * 2u;
            const __half* src = B + (size_t)(k0 + r) * Bs + n0 + c;
            asm volatile("cp.async.cg.shared.global [%0], [%1], 16;" :: "r"(dst), "l"(src));
        }
    };

    const int nst = K / BK;

    issue(0, 0);
    asm volatile("cp.async.commit_group;" ::: "memory");

    for (int s = 0; s < nst; s++) {
        if (s + 1 < nst) {
            issue((s + 1) & 1, (s + 1) * BK);
            asm volatile("cp.async.commit_group;" ::: "memory");
            asm volatile("cp.async.wait_group 1;" ::: "memory");
        } else {
            asm volatile("cp.async.wait_group 0;" ::: "memory");
        }
        __syncthreads();

        const int buf = s & 1;
        const __half* pa = smA + buf * SZA;
        const __half* pb = smB + buf * SZB;
        #pragma unroll
        for (int ks = 0; ks < BK; ks += 16) {
            wmma::fragment<wmma::matrix_a, 16, 16, 16, __half, wmma::row_major> af[FM];
            wmma::fragment<wmma::matrix_b, 16, 16, 16, __half, wmma::row_major> bf[FN];
            #pragma unroll
            for (int i = 0; i < FM; i++)
                wmma::load_matrix_sync(af[i], pa + (wm * WTM + i * 16) * LDA + ks, LDA);
            #pragma unroll
            for (int j = 0; j < FN; j++)
                wmma::load_matrix_sync(bf[j], pb + ks * LDB + wn * WTN + j * 16, LDB);
            #pragma unroll
            for (int i = 0; i < FM; i++)
                #pragma unroll
                for (int j = 0; j < FN; j++)
                    wmma::mma_sync(acc[i][j], af[i], bf[j], acc[i][j]);
        }
        __syncthreads();
    }

    // fused epilogue via per-warp smem patch (pipeline smem is dead)
    // Coalesced mapping: li = e*32 + lane -> lane-consecutive columns.
    float* patch = (float*)dsm + warp * (16 * 20);
    #pragma unroll
    for (int i = 0; i < FM; i++)
        #pragma unroll
        for (int j = 0; j < FN; j++) {
            wmma::store_matrix_sync(patch, acc[i][j], 20, wmma::mem_row_major);
            __syncwarp();
            const int rg0 = m0 + wm * WTM + i * 16;
            const int cg0 = n0 + wn * WTN + j * 16;
            #pragma unroll
            for (int e = 0; e < 8; e++) {
                int li  = e * 32 + lane;
                int r   = li >> 4;
                int c   = li & 15;
                int col = cg0 + c;
                if (col < N) {
                    size_t gi = (size_t)(rg0 + r) * N + col;
                    float v = patch[r * 20 + c] + bias[col];
                    if (MODE == 1) v = 0.5f * v * (1.0f + erff(v * 0.70710678118654752f));
                    if (MODE == 2) v += res[gi];
                    stval(C, gi, v);
                }
            }
            __syncwarp();
        }
}

// smem bytes for a config
#define GSMEM(BM_, BN_, BK_) (2 * ((BM_) * ((BK_) + 8) + (BK_) * ((BN_) + 8)) * 2)

// ---------------- fused flash attention (double-buffered K/V) ----------------
// One CTA = (b, h, 64-row q tile). 4 warps. qkv fp16 in, O fp16 out.
// smem: Q 64x72, K[2]/V[2] 64x72, Ph 64x72 (half); Sf/Of 64x68 (float); m/l.
#define ATT_SMEM ((1 + 2 + 2 + 1) * 64 * 72 * 2 + 2 * 64 * 68 * 4 + 2 * 64 * 4)

__global__ __launch_bounds__(128) void fattn_k(const __half* __restrict__ qkv,
                                               __half* __restrict__ o) {
    int bh = blockIdx.y;
    int b  = bh >> 3;
    int h  = bh & 7;
    int q0 = blockIdx.x << 6;
    int tid = threadIdx.x, warp = tid >> 5, lane = tid & 31;

    extern __shared__ char smem[];
    __half* Qs = (__half*)smem;               // 64*72
    __half* Ks = Qs + 4608;                   // 2 x 64*72
    __half* Vs = Ks + 2 * 4608;               // 2 x 64*72
    __half* Ph = Vs + 2 * 4608;               // 64*72
    float*  Sf = (float*)(Ph + 4608);         // 64*68
    float*  Of = Sf + 64 * 68;
    float*  mrow = Of + 64 * 68;
    float*  lrow = mrow + 64;

    const uint32_t sQ = (uint32_t)__cvta_generic_to_shared(Qs);
    const uint32_t sK = (uint32_t)__cvta_generic_to_shared(Ks);
    const uint32_t sV = (uint32_t)__cvta_generic_to_shared(Vs);

    // Q tile (group 0)
    #pragma unroll
    for (int i = 0; i < 4; i++) {
        int idx = tid + i * 128;
        int r = idx >> 3, c = (idx & 7) * 8;
        uint32_t dst = sQ + (uint32_t)(r * 72 + c) * 2u;
        const __half* src = qkv + ((size_t)(b * TN + q0 + r)) * 1536 + h * 64 + c;
        asm volatile("cp.async.cg.shared.global [%0], [%1], 16;" :: "r"(dst), "l"(src));
    }
    asm volatile("cp.async.commit_group;" ::: "memory");

    auto issueKV = [&](int j) {
        const int j0 = j << 6;
        const int bf = (j & 1) * 4608;
        #pragma unroll
        for (int i = 0; i < 4; i++) {
            int idx = tid + i * 128;
            int r = idx >> 3, c = (idx & 7) * 8;
            const __half* srcK = qkv + ((size_t)(b * TN + j0 + r)) * 1536 + 512 + h * 64 + c;
            const __half* srcV = qkv + ((size_t)(b * TN + j0 + r)) * 1536 + 1024 + h * 64 + c;
            uint32_t dK = sK + (uint32_t)(bf + r * 72 + c) * 2u;
            uint32_t dV = sV + (uint32_t)(bf + r * 72 + c) * 2u;
            asm volatile("cp.async.cg.shared.global [%0], [%1], 16;" :: "r"(dK), "l"(srcK));
            asm volatile("cp.async.cg.shared.global [%0], [%1], 16;" :: "r"(dV), "l"(srcV));
        }
    };

    issueKV(0);
    asm volatile("cp.async.commit_group;" ::: "memory");

    for (int i = tid; i < 64 * 68; i += 128) Of[i] = 0.0f;
    if (tid < 64) { mrow[tid] = -1e30f; lrow[tid] = 0.0f; }

    const int jmax = q0 >> 6;
    for (int j = 0; j <= jmax; j++) {
        // prefetch next K/V tile; safe: buffer (j+1)&1 last read in iter j-1,
        // whose trailing __syncthreads all threads have passed.
        if (j < jmax) {
            issueKV(j + 1);
            asm volatile("cp.async.commit_group;" ::: "memory");
            asm volatile("cp.async.wait_group 1;" ::: "memory");
        } else {
            asm volatile("cp.async.wait_group 0;" ::: "memory");
        }
        __syncthreads();

        const __half* Kc = Ks + (j & 1) * 4608;
        const __half* Vc = Vs + (j & 1) * 4608;

        // S = Q @ K^T (fp32 acc), warp w -> rows [w*16, w*16+16)
        {
            wmma::fragment<wmma::matrix_a, 16, 16, 16, __half, wmma::row_major> af;
            wmma::fragment<wmma::matrix_b, 16, 16, 16, __half, wmma::col_major> bf;
            wmma::fragment<wmma::accumulator, 16, 16, 16, float> ac[4];
            #pragma unroll
            for (int n = 0; n < 4; n++) wmma::fill_fragment(ac[n], 0.0f);
            #pragma unroll
            for (int k = 0; k < 4; k++) {
                wmma::load_matrix_sync(af, Qs + (warp * 16) * 72 + k * 16, 72);
                #pragma unroll
                for (int n = 0; n < 4; n++) {
                    wmma::load_matrix_sync(bf, Kc + (n * 16) * 72 + k * 16, 72);
                    wmma::mma_sync(ac[n], af, bf, ac[n]);
                }
            }
            #pragma unroll
            for (int n = 0; n < 4; n++)
                wmma::store_matrix_sync(Sf + (warp * 16) * 68 + n * 16, ac[n], 68,
                                        wmma::mem_row_major);
        }
        __syncthreads();

        // online softmax: 2 threads per row
        {
            int r  = tid >> 1;
            int hc = (tid & 1) * 32;
            bool diag = (j == jmax);
            float* srow = Sf + r * 68 + hc;
            float sv[32];
            float lm = -1e30f;
            #pragma unroll
            for (int c = 0; c < 32; c++) {
                float s = srow[c] * 0.125f;
                if (diag && (hc + c) > r) s = -1e30f;
                sv[c] = s;
                lm = fmaxf(lm, s);
            }
            float mt = fmaxf(lm, __shfl_xor_sync(0xffffffffu, lm, 1));
            float mo = mrow[r];
            float mn = fmaxf(mo, mt);
            float fs = expf(mo - mn);
            float sum = 0.0f;
            __half* prow = Ph + r * 72 + hc;
            #pragma unroll
            for (int c = 0; c < 32; c++) {
                float p = expf(sv[c] - mn);
                prow[c] = __float2half(p);
                sum += p;
            }
            sum += __shfl_xor_sync(0xffffffffu, sum, 1);
            float* orow = Of + r * 68 + hc;
            #pragma unroll
            for (int c = 0; c < 32; c++) orow[c] *= fs;
            __syncwarp();
            if ((tid & 1) == 0) {
                mrow[r] = mn;
                lrow[r] = lrow[r] * fs + sum;
            }
        }
        __syncthreads();

        // O += P @ V
        {
            wmma::fragment<wmma::matrix_a, 16, 16, 16, __half, wmma::row_major> af;
            wmma::fragment<wmma::matrix_b, 16, 16, 16, __half, wmma::row_major> bf;
            wmma::fragment<wmma::accumulator, 16, 16, 16, float> ac;
            #pragma unroll
            for (int n = 0; n < 4; n++) {
                wmma::load_matrix_sync(ac, Of + (warp * 16) * 68 + n * 16, 68,
                                       wmma::mem_row_major);
                #pragma unroll
                for (int k = 0; k < 4; k++) {
                    wmma::load_matrix_sync(af, Ph + (warp * 16) * 72 + k * 16, 72);
                    wmma::load_matrix_sync(bf, Vc + (k * 16) * 72 + n * 16, 72);
                    wmma::mma_sync(ac, af, bf, ac);
                }
                wmma::store_matrix_sync(Of + (warp * 16) * 68 + n * 16, ac, 68,
                                        wmma::mem_row_major);
            }
        }
        __syncthreads();
    }

    // epilogue: O / l -> fp16, coalesced 16B stores
    #pragma unroll
    for (int i = 0; i < 4; i++) {
        int idx = tid + i * 128;
        int r = idx >> 3, c0 = (idx & 7) * 8;
        float inv = 1.0f / lrow[r];
        const float* orow = Of + r * 68 + c0;
        __half2 hv[4];
        #pragma unroll
        for (int k = 0; k < 4; k++)
            hv[k] = __halves2half2(__float2half(orow[k * 2] * inv),
                                   __float2half(orow[k * 2 + 1] * inv));
        *(uint4*)(o + ((size_t)(b * TN + q0 + r)) * DM + h * 64 + c0) = *(uint4*)hv;
    }
}

// ---------------- launch ----------------
extern "C" void kernel_launch(void* const* d_in, const int* in_sizes, int n_in,
                              void* d_out, int out_size) {
    const int*   x      = (const int*)  d_in[0];
    const float* tok    = (const float*)d_in[1];
    const float* pos    = (const float*)d_in[2];
    const float* qkv_w  = (const float*)d_in[3];
    const float* qkv_b  = (const float*)d_in[4];
    const float* out_w  = (const float*)d_in[5];
    const float* out_b  = (const float*)d_in[6];
    const float* ln1_s  = (const float*)d_in[7];
    const float* ln1_b  = (const float*)d_in[8];
    const float* ff1_w  = (const float*)d_in[9];
    const float* ff1_b  = (const float*)d_in[10];
    const float* ff2_w  = (const float*)d_in[11];
    const float* ff2_b  = (const float*)d_in[12];
    const float* ln2_s  = (const float*)d_in[13];
    const float* ln2_b  = (const float*)d_in[14];
    const float* lnf_s  = (const float*)d_in[15];
    const float* lnf_b  = (const float*)d_in[16];
    const float* head_w = (const float*)d_in[17];
    const float* head_b = (const float*)d_in[18];
    float* out = (float*)d_out;

    float *h;
    __half *tmpH, *qkvA, *attH, *ffH, *qkvH, *outH, *ff1H, *ff2H, *headH;
    cudaGetSymbolAddress((void**)&h,    g_h);
    cudaGetSymbolAddress((void**)&tmpH, g_tmpH);
    cudaGetSymbolAddress((void**)&qkvA, g_qkvA);
    cudaGetSymbolAddress((void**)&attH, g_attH);
    cudaGetSymbolAddress((void**)&ffH,  g_ffH);
    cudaGetSymbolAddress((void**)&qkvH, g_qkvH);
    cudaGetSymbolAddress((void**)&outH, g_outH);
    cudaGetSymbolAddress((void**)&ff1H, g_ff1H);
    cudaGetSymbolAddress((void**)&ff2H, g_ff2H);
    cudaGetSymbolAddress((void**)&headH,g_headH);

    const int M = BS * TN;  // 2048
    const int SMBIG = GSMEM(128, 128, 64);   // 71680 B
    const int SMSML = GSMEM(64, 64, 64);     // 36864 B

    cudaFuncSetAttribute(gemmh<128,128,64,128,2,2,0,__half>, cudaFuncAttributeMaxDynamicSharedMemorySize, SMBIG);
    cudaFuncSetAttribute(gemmh<128,128,64,128,2,2,1,__half>, cudaFuncAttributeMaxDynamicSharedMemorySize, SMBIG);
    cudaFuncSetAttribute(gemmh<128,128,64,128,2,2,0,float>,  cudaFuncAttributeMaxDynamicSharedMemorySize, SMBIG);
    cudaFuncSetAttribute(gemmh<64,64,64,128,2,2,2,float>,    cudaFuncAttributeMaxDynamicSharedMemorySize, SMSML);
    cudaFuncSetAttribute(fattn_k, cudaFuncAttributeMaxDynamicSharedMemorySize, ATT_SMEM);

    // weight conversions (fp32 -> fp16), 4 elems/thread
    {
        int n4;
        n4 = LN_*DM*3*DM/4;  convh_k<<<(n4+255)/256, 256>>>(qkv_w, qkvH, n4);
        n4 = LN_*DM*DM/4;    convh_k<<<(n4+255)/256, 256>>>(out_w, outH, n4);
        n4 = LN_*DM*4*DM/4;  convh_k<<<(n4+255)/256, 256>>>(ff1_w, ff1H, n4);
        n4 = LN_*4*DM*DM/4;  convh_k<<<(n4+255)/256, 256>>>(ff2_w, ff2H, n4);
        convpad_k<<<dim3((VNP/4+255)/256, DM), 256>>>(head_w, headH);
    }

    embed_k<<<(BS*TN*DM + 255) / 256, 256>>>(x, tok, pos, h);

    for (int l = 0; l < LN_; l++) {
        const __half* wq = qkvH + (size_t)l * DM * 3*DM;
        const __half* wo = outH + (size_t)l * DM * DM;
        const __half* w1 = ff1H + (size_t)l * DM * 4*DM;
        const __half* w2 = ff2H + (size_t)l * 4*DM * DM;
        const float* bq = qkv_b + (size_t)l * 3*DM;
        const float* bo = out_b + (size_t)l * DM;
        const float* b1 = ff1_b + (size_t)l * 4*DM;
        const float* b2 = ff2_b + (size_t)l * DM;

        // attention block
        ln_k<<<M / 8, 256>>>(h, tmpH, ln1_s + l * DM, ln1_b + l * DM);
        gemmh<128,128,64,128,2,2,0,__half><<<dim3(16, 12), 128, SMBIG>>>(tmpH, wq, bq, nullptr, qkvA, M, 3*DM, DM, 3*DM);
        fattn_k<<<dim3(8, 32), 128, ATT_SMEM>>>(qkvA, attH);
        gemmh<64,64,64,128,2,2,2,float><<<dim3(32, 8), 128, SMSML>>>(attH, wo, bo, h, h, M, DM, DM, DM);

        // feed-forward block
        ln_k<<<M / 8, 256>>>(h, tmpH, ln2_s + l * DM, ln2_b + l * DM);
        gemmh<128,128,64,128,2,2,1,__half><<<dim3(16, 16), 128, SMBIG>>>(tmpH, w1, b1, nullptr, ffH, M, 4*DM, DM, 4*DM);
        gemmh<64,64,64,128,2,2,2,float><<<dim3(32, 8), 128, SMSML>>>(ffH, w2, b2, h, h, M, DM, 4*DM, DM);
    }

    // final LN + LM head
    ln_k<<<M / 8, 256>>>(h, tmpH, lnf_s, lnf_b);
    gemmh<128,128,64,128,2,2,0,float><<<dim3(16, VNP / 128), 128, SMBIG>>>(tmpH, headH, head_b, nullptr, out, M, VN, DM, VNP);
}